// round 13
// baseline (speedup 1.0000x reference)
#include <cuda_runtime.h>
#include <cuda_fp16.h>
#include <cstdint>
#include <math.h>

#define LSEQ 4096
#define DM   1024
#define BB   8
#define NF   4096          // complex FFT size (real FFT of 8192 via packing)
#define MH   4096          // half of 8192
#define SBUF 4352          // padded in-place buffer: 17 * 256 float2

// padded index map (avoids 128B-stride bank conflicts)
#define PHI(i) ((((i) >> 4) * 17) + ((i) & 15))

// ---------------- device scratch (no allocations allowed) ----------------
__device__ float2  g_Kf[DM * (MH + 1)];                 // kernel spectra (pre-scaled by 1/4096)
__device__ __half  g_gh[(size_t)BB * DM * LSEQ];        // gelu output as fp16
__device__ __half  g_Wh[DM * DM];                       // W as fp16
__device__ float2  g_tw[NF / 2];                        // e^{-2pi i j/4096}
__device__ float2  g_tw2[MH / 2 + 1];                   // e^{-2pi i k/8192}

__device__ __forceinline__ float2 cmulf(float2 a, float2 b) {
    return make_float2(a.x * b.x - a.y * b.y, a.x * b.y + a.y * b.x);
}

// ---------------- fused init: twiddle tables + W->fp16 ----------------
__global__ void init_all_kernel(const float* __restrict__ W) {
    int i = blockIdx.x * blockDim.x + threadIdx.x;
    if (i < NF / 2) {
        float a = (float)i / (float)(NF / 2);
        g_tw[i] = make_float2(cospif(a), -sinpif(a));
    }
    if (i <= MH / 2) {
        float a = (float)i / (float)MH;
        g_tw2[i] = make_float2(cospif(a), -sinpif(a));
    }
    if (i < DM * DM) g_Wh[i] = __float2half(W[i]);
}

// ---------------- in-place 16-point DFT (two radix-4 stages) ----------------
template<int DIR, bool HZ>
__device__ __forceinline__ void dft16ip(float2* c) {
    const float d  = (float)DIR;
    const float C1 = 0.92387953251128674f;
    const float Sn = 0.38268343236508978f;
    const float HF = 0.70710678118654752f;
#pragma unroll
    for (int r1 = 0; r1 < 4; r1++) {
        float2 a = c[r1], b = c[r1 + 4];
        if (HZ) {
            c[r1]      = make_float2(a.x + b.x, a.y + b.y);
            c[r1 + 4]  = make_float2(a.x + d * b.y, a.y - d * b.x);
            c[r1 + 8]  = make_float2(a.x - b.x, a.y - b.y);
            c[r1 + 12] = make_float2(a.x - d * b.y, a.y + d * b.x);
        } else {
            float2 e = c[r1 + 8], f = c[r1 + 12];
            float2 t0 = make_float2(a.x + e.x, a.y + e.y);
            float2 t1 = make_float2(a.x - e.x, a.y - e.y);
            float2 t2 = make_float2(b.x + f.x, b.y + f.y);
            float2 t3 = make_float2(b.x - f.x, b.y - f.y);
            c[r1]      = make_float2(t0.x + t2.x, t0.y + t2.y);
            c[r1 + 8]  = make_float2(t0.x - t2.x, t0.y - t2.y);
            c[r1 + 4]  = make_float2(t1.x + d * t3.y, t1.y - d * t3.x);
            c[r1 + 12] = make_float2(t1.x - d * t3.y, t1.y + d * t3.x);
        }
    }
    const float2 e1 = make_float2(C1,  -d * Sn);
    const float2 e2 = make_float2(HF,  -d * HF);
    const float2 e3 = make_float2(Sn,  -d * C1);
    const float2 e6 = make_float2(-HF, -d * HF);
    const float2 e9 = make_float2(-C1,  d * Sn);
    c[5]  = cmulf(c[5],  e1);
    c[9]  = cmulf(c[9],  e2);
    c[13] = cmulf(c[13], e3);
    c[6]  = cmulf(c[6],  e2);
    c[10] = make_float2(d * c[10].y, -d * c[10].x);
    c[14] = cmulf(c[14], e6);
    c[7]  = cmulf(c[7],  e3);
    c[11] = cmulf(c[11], e6);
    c[15] = cmulf(c[15], e9);
#pragma unroll
    for (int m2 = 0; m2 < 4; m2++) {
        float2 u0 = c[4 * m2], u1 = c[4 * m2 + 1], u2 = c[4 * m2 + 2], u3 = c[4 * m2 + 3];
        float2 t0 = make_float2(u0.x + u2.x, u0.y + u2.y);
        float2 t1 = make_float2(u0.x - u2.x, u0.y - u2.y);
        float2 t2 = make_float2(u1.x + u3.x, u1.y + u3.y);
        float2 t3 = make_float2(u1.x - u3.x, u1.y - u3.y);
        c[4 * m2]     = make_float2(t0.x + t2.x, t0.y + t2.y);
        c[4 * m2 + 2] = make_float2(t0.x - t2.x, t0.y - t2.y);
        c[4 * m2 + 1] = make_float2(t1.x + d * t3.y, t1.y - d * t3.x);
        c[4 * m2 + 3] = make_float2(t1.x - d * t3.y, t1.y + d * t3.x);
    }
}

__device__ __forceinline__ void store_tw(float2* s, int wbase, int stride,
                                         float2 w1, const float2* c) {
    float2 w2 = cmulf(w1, w1);
    float2 w4 = cmulf(w2, w2);
    float2 gw = make_float2(1.f, 0.f);
#pragma unroll
    for (int b = 0; b < 4; b++) {
        float2 w = gw;
        s[wbase + stride * (4 * b + 0)] = cmulf(w, c[b]);
        w = cmulf(w, w1);
        s[wbase + stride * (4 * b + 1)] = cmulf(w, c[4 + b]);
        w = cmulf(w, w1);
        s[wbase + stride * (4 * b + 2)] = cmulf(w, c[8 + b]);
        w = cmulf(w, w1);
        s[wbase + stride * (4 * b + 3)] = cmulf(w, c[12 + b]);
        gw = cmulf(gw, w4);
    }
}

template<int DIR, bool HZ>
__device__ __forceinline__ void fft4096_ip(float2* s, int tid) {
    float2 c[16];
    const int rb = PHI(tid);
    {
#pragma unroll
        for (int m = 0; m < (HZ ? 8 : 16); m++) c[m] = s[rb + 272 * m];
        dft16ip<DIR, HZ>(c);
        float2 w1 = g_tw[tid];
        if (DIR < 0) w1.y = -w1.y;
        __syncthreads();
        store_tw(s, 17 * tid, 1, w1, c);
        __syncthreads();
    }
    {
#pragma unroll
        for (int m = 0; m < 16; m++) c[m] = s[rb + 272 * m];
        dft16ip<DIR, false>(c);
        float2 w1 = g_tw[tid & ~15];
        if (DIR < 0) w1.y = -w1.y;
        __syncthreads();
        store_tw(s, 17 * (tid & ~15) + (tid & 15), 17, w1, c);
        __syncthreads();
    }
    {
        // pass 2: each thread reads and writes the SAME address set -> no mid-pass sync
#pragma unroll
        for (int m = 0; m < 16; m++) c[m] = s[rb + 272 * m];
        dft16ip<DIR, false>(c);
#pragma unroll
        for (int slot = 0; slot < 16; slot++) {
            int m = 4 * (slot & 3) + (slot >> 2);
            s[rb + 272 * m] = c[slot];
        }
        __syncthreads();
    }
}

// ---------------- build kernel spectrum: interp + norm + rfft ----------------
__global__ void build_kf_kernel(const float* __restrict__ k0, const float* __restrict__ k1,
                                const float* __restrict__ k2, const float* __restrict__ k3,
                                const float* __restrict__ k4, const float* __restrict__ k5,
                                const float* __restrict__ k6) {
    extern __shared__ float2 smem[];
    float2* s = smem;
    __shared__ float red[8];
    int d = blockIdx.x;
    int tid = threadIdx.x;

    const float* segp[7] = {k0, k1, k2, k3, k4, k5, k6};

    float ss = 0.f;
    for (int t = tid; t < LSEQ; t += 256) {
        int seg, scale, off;
        if      (t < 64)   { seg = 0; scale = 1;  off = 0;    }
        else if (t < 128)  { seg = 1; scale = 1;  off = 64;   }
        else if (t < 256)  { seg = 2; scale = 2;  off = 128;  }
        else if (t < 512)  { seg = 3; scale = 4;  off = 256;  }
        else if (t < 1024) { seg = 4; scale = 8;  off = 512;  }
        else if (t < 2048) { seg = 5; scale = 16; off = 1024; }
        else               { seg = 6; scale = 32; off = 2048; }
        int j = t - off;
        float coord = ((float)j + 0.5f) / (float)scale - 0.5f;
        coord = fminf(fmaxf(coord, 0.f), 63.f);
        int lo = (int)coord;
        int hi = min(lo + 1, 63);
        float w = coord - (float)lo;
        const float* kp = segp[seg] + d * 64;
        float v = kp[lo] * (1.f - w) + kp[hi] * w;
        ((float*)s)[2 * PHI(t >> 1) + (t & 1)] = v;
        ss += v * v;
    }
    for (int o = 16; o > 0; o >>= 1) ss += __shfl_xor_sync(0xffffffffu, ss, o);
    if ((tid & 31) == 0) red[tid >> 5] = ss;
    __syncthreads();
    float tot = 0.f;
#pragma unroll
    for (int i = 0; i < 8; i++) tot += red[i];
    float sc = 1.0f / sqrtf(tot);

    for (int n = tid; n < NF / 2; n += 256) {
        float2 z = s[PHI(n)];
        s[PHI(n)] = make_float2(z.x * sc, z.y * sc);
    }
    __syncthreads();
    fft4096_ip<1, true>(s, tid);

    const float INV = 1.0f / 4096.0f;
    float2* Kf = g_Kf + (size_t)d * (MH + 1);
    for (int k = tid; k <= 2048; k += 256) {
        if (k == 0) {
            float2 Z0 = s[PHI(0)];
            Kf[0]  = make_float2((Z0.x + Z0.y) * INV, 0.f);
            Kf[MH] = make_float2((Z0.x - Z0.y) * INV, 0.f);
        } else if (k == 2048) {
            float2 Z = s[PHI(2048)];
            Kf[2048] = make_float2(Z.x * INV, -Z.y * INV);
        } else {
            float2 Za = s[PHI(k)], Zb = s[PHI(NF - k)];
            float2 E  = make_float2(0.5f * (Za.x + Zb.x), 0.5f * (Za.y - Zb.y));
            float2 Dm = make_float2(0.5f * (Za.x - Zb.x), 0.5f * (Za.y + Zb.y));
            float2 O  = make_float2(Dm.y, -Dm.x);
            float2 w  = g_tw2[k];
            float2 WO = cmulf(w, O);
            Kf[k]      = make_float2((E.x + WO.x) * INV, (E.y + WO.y) * INV);
            Kf[MH - k] = make_float2((E.x - WO.x) * INV, -(E.y - WO.y) * INV);
        }
    }
}

// ---------------- per-row conv ----------------
__global__ void __launch_bounds__(256, 4) conv_kernel(const float* __restrict__ u,
                                                      const float* __restrict__ Dv) {
    extern __shared__ float2 smem[];
    float2* s = smem;
    int row = blockIdx.x;            // b*DM + d
    int d = row & (DM - 1);
    int tid = threadIdx.x;
    const float2* u2 = (const float2*)(u + (size_t)row * LSEQ);

    for (int n = tid; n < 2048; n += 256) s[PHI(n)] = u2[n];
    __syncthreads();
    fft4096_ip<1, true>(s, tid);

    const float2* Kf = g_Kf + (size_t)d * (MH + 1);
    for (int k = tid; k <= 2048; k += 256) {
        if (k == 0) {
            float2 Z0 = s[PHI(0)];
            float X0 = Z0.x + Z0.y;
            float XM = Z0.x - Z0.y;
            float2 K0 = Kf[0], KM = Kf[MH];
            float2 Y0 = make_float2(X0 * K0.x, X0 * K0.y);
            float2 YM = make_float2(XM * KM.x, XM * KM.y);
            float2 Ep = make_float2(0.5f * (Y0.x + YM.x), 0.5f * (Y0.y - YM.y));
            float2 Op = make_float2(0.5f * (Y0.x - YM.x), 0.5f * (Y0.y + YM.y));
            s[PHI(0)] = make_float2(Ep.x - Op.y, Ep.y + Op.x);
        } else if (k == 2048) {
            float2 Z = s[PHI(2048)];
            float2 X = make_float2(Z.x, -Z.y);
            float2 Y = cmulf(X, Kf[2048]);
            s[PHI(2048)] = make_float2(Y.x, -Y.y);
        } else {
            float2 Za = s[PHI(k)], Zb = s[PHI(NF - k)];
            float2 E  = make_float2(0.5f * (Za.x + Zb.x), 0.5f * (Za.y - Zb.y));
            float2 Dm = make_float2(0.5f * (Za.x - Zb.x), 0.5f * (Za.y + Zb.y));
            float2 O  = make_float2(Dm.y, -Dm.x);
            float2 w  = g_tw2[k];
            float2 WO = cmulf(w, O);
            float2 Xa = make_float2(E.x + WO.x, E.y + WO.y);
            float2 Xb = make_float2(E.x - WO.x, -(E.y - WO.y));
            float2 Ya = cmulf(Xa, Kf[k]);
            float2 Yb = cmulf(Xb, Kf[MH - k]);
            float2 Ep = make_float2(0.5f * (Ya.x + Yb.x), 0.5f * (Ya.y - Yb.y));
            float2 Dp = make_float2(0.5f * (Ya.x - Yb.x), 0.5f * (Ya.y + Yb.y));
            float2 V  = make_float2(w.x, -w.y);
            float2 Op = cmulf(V, Dp);
            s[PHI(k)]      = make_float2(Ep.x - Op.y, Ep.y + Op.x);
            s[PHI(NF - k)] = make_float2(Ep.x + Op.y, Op.x - Ep.y);
        }
    }
    __syncthreads();
    fft4096_ip<-1, false>(s, tid);

    float Dd = Dv[d];
    __half2* gout = (__half2*)(g_gh + (size_t)row * LSEQ);
#pragma unroll 1
    for (int n = tid; n < 2048; n += 256) {
        float2 z = s[PHI(n)];
        float2 uu = u2[n];
        float x0 = z.x + uu.x * Dd;
        float x1 = z.y + uu.y * Dd;
        float g0 = 0.5f * x0 * (1.f + erff(x0 * 0.70710678118654752f));
        float g1 = 0.5f * x1 * (1.f + erff(x1 * 0.70710678118654752f));
        gout[n] = __floats2half2_rn(g0, g1);
    }
}

// ---------------- fp16 tensor-core GEMM: out[b,v,l] = sum_u W[v,u] g[b,u,l] + bias[v] ----
// m16n8k16; BM=128 x BN=256 x BK=64, 512 threads (2x8 warps), 3-stage cp.async.
#define BM 128
#define BN 256
#define BK 64
#define NTH 512
#define SAH 72    // A row stride (halves): [v][kk]
#define SBH 264   // B row stride (halves): [kk][l] (528B row, conflict profile same as 272B)
#define A_SZH (BM * SAH)             // 9216 halves
#define B_SZH (BK * SBH)             // 16896 halves
#define STG_H (A_SZH + B_SZH)        // 26112 halves = 52224 B
#define NSTG 3
#define SMEM_GEMM (NSTG * STG_H * 2) // 156672 B
#define NIT (DM / BK)                // 16

__device__ __forceinline__ void cpa16(void* s, const void* g) {
    unsigned sa = (unsigned)__cvta_generic_to_shared(s);
    asm volatile("cp.async.cg.shared.global [%0], [%1], 16;\n" :: "r"(sa), "l"(g));
}
__device__ __forceinline__ void ldsm4(unsigned& r0, unsigned& r1, unsigned& r2, unsigned& r3,
                                      const void* p) {
    unsigned a = (unsigned)__cvta_generic_to_shared(p);
    asm volatile("ldmatrix.sync.aligned.m8n8.x4.shared.b16 {%0,%1,%2,%3}, [%4];\n"
                 : "=r"(r0), "=r"(r1), "=r"(r2), "=r"(r3) : "r"(a));
}
__device__ __forceinline__ void ldsm4t(unsigned& r0, unsigned& r1, unsigned& r2, unsigned& r3,
                                       const void* p) {
    unsigned a = (unsigned)__cvta_generic_to_shared(p);
    asm volatile("ldmatrix.sync.aligned.m8n8.x4.trans.shared.b16 {%0,%1,%2,%3}, [%4];\n"
                 : "=r"(r0), "=r"(r1), "=r"(r2), "=r"(r3) : "r"(a));
}

__global__ void __launch_bounds__(NTH, 1) gemm_kernel(const float* __restrict__ bias,
                                                      float* __restrict__ out) {
    extern __shared__ __half hsm[];

    int b  = blockIdx.z;
    int v0 = blockIdx.y * BM;
    int l0 = blockIdx.x * BN;
    int tid = threadIdx.x;
    int wid = tid >> 5, lane = tid & 31;
    int wm = wid >> 3, wn = wid & 7;         // 2x8 warp grid; warp tile 64(v) x 32(l)
    int grp = lane >> 2, qid = lane & 3;

    const __half* gbase = g_gh + (size_t)b * DM * LSEQ;

    float acc[4][4][4];
#pragma unroll
    for (int i = 0; i < 4; i++)
#pragma unroll
        for (int j = 0; j < 4; j++)
#pragma unroll
            for (int r = 0; r < 4; r++) acc[i][j][r] = 0.f;

    auto stage_load = [&](int st, int u0) {
        __half* As = hsm + st * STG_H;
        __half* Bs = As + A_SZH;
#pragma unroll
        for (int rep = 0; rep < 2; rep++) {          // A: 128 rows x 64 halves (8 x 16B/row)
            int idx = rep * NTH + tid;
            int r = idx >> 3, c = idx & 7;
            cpa16(As + r * SAH + c * 8, g_Wh + (size_t)(v0 + r) * DM + u0 + c * 8);
        }
#pragma unroll
        for (int rep = 0; rep < 4; rep++) {          // B: 64 rows x 256 halves (32 x 16B/row)
            int idx = rep * NTH + tid;
            int r = idx >> 5, c = idx & 31;
            cpa16(Bs + r * SBH + c * 8, gbase + (size_t)(u0 + r) * LSEQ + l0 + c * 8);
        }
        asm volatile("cp.async.commit_group;\n");
    };

    // prologue: fill 2 of 3 stages
    stage_load(0, 0);
    stage_load(1, BK);

    for (int it = 0; it < NIT; it++) {
        if (it < NIT - 1) {
            asm volatile("cp.async.wait_group 1;\n");   // stage(it) ready
        } else {
            asm volatile("cp.async.wait_group 0;\n");
        }
        __syncthreads();                                // all warps done with stage (it+2)%3
        if (it + 2 < NIT) stage_load((it + 2) % 3, (it + 2) * BK);

        const __half* A   = hsm + (it % 3) * STG_H;
        const __half* Bsm = A + A_SZH;

#pragma unroll
        for (int ks = 0; ks < 4; ks++) {                // four k16 steps per BK=64
            int kk = ks * 16;
            unsigned bf[4][2];
#pragma unroll
            for (int p = 0; p < 2; p++) {
                int mrow = kk + (lane & 7) + ((lane & 8) ? 8 : 0);
                int mcol = wn * 32 + p * 16 + ((lane & 16) ? 8 : 0);
                unsigned r0, r1, r2, r3;
                ldsm4t(r0, r1, r2, r3, Bsm + mrow * SBH + mcol);
                bf[p * 2 + 0][0] = r0; bf[p * 2 + 0][1] = r1;
                bf[p * 2 + 1][0] = r2; bf[p * 2 + 1][1] = r3;
            }
#pragma unroll
            for (int mt = 0; mt < 4; mt++) {
                int rowa = wm * 64 + mt * 16 + (lane & 15);
                int cola = kk + ((lane & 16) ? 8 : 0);
                unsigned a0, a1, a2, a3;
                ldsm4(a0, a1, a2, a3, A + rowa * SAH + cola);
#pragma unroll
                for (int nt = 0; nt < 4; nt++) {
                    asm volatile(
                        "mma.sync.aligned.m16n8k16.row.col.f32.f16.f16.f32 "
                        "{%0,%1,%2,%3}, {%4,%5,%6,%7}, {%8,%9}, {%0,%1,%2,%3};\n"
                        : "+f"(acc[mt][nt][0]), "+f"(acc[mt][nt][1]),
                          "+f"(acc[mt][nt][2]), "+f"(acc[mt][nt][3])
                        : "r"(a0), "r"(a1), "r"(a2), "r"(a3),
                          "r"(bf[nt][0]), "r"(bf[nt][1]));
                }
            }
        }
    }
#pragma unroll
    for (int mt = 0; mt < 4; mt++) {
        int v = v0 + wm * 64 + mt * 16 + grp;
        float bi0 = bias[v], bi1 = bias[v + 8];
#pragma unroll
        for (int nt = 0; nt < 4; nt++) {
            int l = l0 + wn * 32 + nt * 8 + qid * 2;
            float2* o0 = (float2*)(out + ((size_t)b * DM + v) * LSEQ + l);
            float2* o1 = (float2*)(out + ((size_t)b * DM + v + 8) * LSEQ + l);
            *o0 = make_float2(acc[mt][nt][0] + bi0, acc[mt][nt][1] + bi0);
            *o1 = make_float2(acc[mt][nt][2] + bi1, acc[mt][nt][3] + bi1);
        }
    }
}

// ---------------- launch ----------------
extern "C" void kernel_launch(void* const* d_in, const int* in_sizes, int n_in,
                              void* d_out, int out_size) {
    const float* u  = (const float*)d_in[0];
    const float* k0 = (const float*)d_in[1];
    const float* k1 = (const float*)d_in[2];
    const float* k2 = (const float*)d_in[3];
    const float* k3 = (const float*)d_in[4];
    const float* k4 = (const float*)d_in[5];
    const float* k5 = (const float*)d_in[6];
    const float* k6 = (const float*)d_in[7];
    const float* Dv = (const float*)d_in[8];
    const float* W  = (const float*)d_in[9];
    const float* bi = (const float*)d_in[10];
    float* out = (float*)d_out;

    const int smem_fft = SBUF * (int)sizeof(float2);                 // 34816 B
    cudaFuncSetAttribute(conv_kernel, cudaFuncAttributeMaxDynamicSharedMemorySize, smem_fft);
    cudaFuncSetAttribute(build_kf_kernel, cudaFuncAttributeMaxDynamicSharedMemorySize, smem_fft);
    cudaFuncSetAttribute(gemm_kernel, cudaFuncAttributeMaxDynamicSharedMemorySize, SMEM_GEMM);

    init_all_kernel<<<DM * DM / 256, 256>>>(W);
    build_kf_kernel<<<DM, 256, smem_fft>>>(k0, k1, k2, k3, k4, k5, k6);
    conv_kernel<<<BB * DM, 256, smem_fft>>>(u, Dv);
    dim3 gg(LSEQ / BN, DM / BM, BB);
    gemm_kernel<<<gg, NTH, SMEM_GEMM>>>(bi, out);
}

// round 14
// speedup vs baseline: 1.0336x; 1.0336x over previous
#include <cuda_runtime.h>
#include <cuda_fp16.h>
#include <cstdint>
#include <math.h>

#define LSEQ 4096
#define DM   1024
#define BB   8
#define NF   4096          // complex FFT size (real FFT of 8192 via packing)
#define MH   4096          // half of 8192
#define SBUF 4352          // padded in-place buffer: 17 * 256 float2

// padded index map (avoids 128B-stride bank conflicts)
#define PHI(i) ((((i) >> 4) * 17) + ((i) & 15))

// ---------------- device scratch (no allocations allowed) ----------------
__device__ float2  g_Kf[DM * (MH + 1)];                 // kernel spectra (pre-scaled by 1/4096)
__device__ __half  g_gh[(size_t)BB * DM * LSEQ];        // gelu output as fp16
__device__ __half  g_Wh[DM * DM];                       // W as fp16
__device__ float2  g_tw[NF / 2];                        // e^{-2pi i j/4096}
__device__ float2  g_tw2[MH / 2 + 1];                   // e^{-2pi i k/8192}

__device__ __forceinline__ float2 cmulf(float2 a, float2 b) {
    return make_float2(a.x * b.x - a.y * b.y, a.x * b.y + a.y * b.x);
}

// ---------------- fused init: twiddle tables + W->fp16 ----------------
__global__ void init_all_kernel(const float* __restrict__ W) {
    int i = blockIdx.x * blockDim.x + threadIdx.x;
    if (i < NF / 2) {
        float a = (float)i / (float)(NF / 2);
        g_tw[i] = make_float2(cospif(a), -sinpif(a));
    }
    if (i <= MH / 2) {
        float a = (float)i / (float)MH;
        g_tw2[i] = make_float2(cospif(a), -sinpif(a));
    }
    if (i < DM * DM) g_Wh[i] = __float2half(W[i]);
}

// ---------------- in-place 16-point DFT (two radix-4 stages) ----------------
template<int DIR, bool HZ>
__device__ __forceinline__ void dft16ip(float2* c) {
    const float d  = (float)DIR;
    const float C1 = 0.92387953251128674f;
    const float Sn = 0.38268343236508978f;
    const float HF = 0.70710678118654752f;
#pragma unroll
    for (int r1 = 0; r1 < 4; r1++) {
        float2 a = c[r1], b = c[r1 + 4];
        if (HZ) {
            c[r1]      = make_float2(a.x + b.x, a.y + b.y);
            c[r1 + 4]  = make_float2(a.x + d * b.y, a.y - d * b.x);
            c[r1 + 8]  = make_float2(a.x - b.x, a.y - b.y);
            c[r1 + 12] = make_float2(a.x - d * b.y, a.y + d * b.x);
        } else {
            float2 e = c[r1 + 8], f = c[r1 + 12];
            float2 t0 = make_float2(a.x + e.x, a.y + e.y);
            float2 t1 = make_float2(a.x - e.x, a.y - e.y);
            float2 t2 = make_float2(b.x + f.x, b.y + f.y);
            float2 t3 = make_float2(b.x - f.x, b.y - f.y);
            c[r1]      = make_float2(t0.x + t2.x, t0.y + t2.y);
            c[r1 + 8]  = make_float2(t0.x - t2.x, t0.y - t2.y);
            c[r1 + 4]  = make_float2(t1.x + d * t3.y, t1.y - d * t3.x);
            c[r1 + 12] = make_float2(t1.x - d * t3.y, t1.y + d * t3.x);
        }
    }
    const float2 e1 = make_float2(C1,  -d * Sn);
    const float2 e2 = make_float2(HF,  -d * HF);
    const float2 e3 = make_float2(Sn,  -d * C1);
    const float2 e6 = make_float2(-HF, -d * HF);
    const float2 e9 = make_float2(-C1,  d * Sn);
    c[5]  = cmulf(c[5],  e1);
    c[9]  = cmulf(c[9],  e2);
    c[13] = cmulf(c[13], e3);
    c[6]  = cmulf(c[6],  e2);
    c[10] = make_float2(d * c[10].y, -d * c[10].x);
    c[14] = cmulf(c[14], e6);
    c[7]  = cmulf(c[7],  e3);
    c[11] = cmulf(c[11], e6);
    c[15] = cmulf(c[15], e9);
#pragma unroll
    for (int m2 = 0; m2 < 4; m2++) {
        float2 u0 = c[4 * m2], u1 = c[4 * m2 + 1], u2 = c[4 * m2 + 2], u3 = c[4 * m2 + 3];
        float2 t0 = make_float2(u0.x + u2.x, u0.y + u2.y);
        float2 t1 = make_float2(u0.x - u2.x, u0.y - u2.y);
        float2 t2 = make_float2(u1.x + u3.x, u1.y + u3.y);
        float2 t3 = make_float2(u1.x - u3.x, u1.y - u3.y);
        c[4 * m2]     = make_float2(t0.x + t2.x, t0.y + t2.y);
        c[4 * m2 + 2] = make_float2(t0.x - t2.x, t0.y - t2.y);
        c[4 * m2 + 1] = make_float2(t1.x + d * t3.y, t1.y - d * t3.x);
        c[4 * m2 + 3] = make_float2(t1.x - d * t3.y, t1.y + d * t3.x);
    }
}

__device__ __forceinline__ void store_tw(float2* s, int wbase, int stride,
                                         float2 w1, const float2* c) {
    float2 w2 = cmulf(w1, w1);
    float2 w4 = cmulf(w2, w2);
    float2 gw = make_float2(1.f, 0.f);
#pragma unroll
    for (int b = 0; b < 4; b++) {
        float2 w = gw;
        s[wbase + stride * (4 * b + 0)] = cmulf(w, c[b]);
        w = cmulf(w, w1);
        s[wbase + stride * (4 * b + 1)] = cmulf(w, c[4 + b]);
        w = cmulf(w, w1);
        s[wbase + stride * (4 * b + 2)] = cmulf(w, c[8 + b]);
        w = cmulf(w, w1);
        s[wbase + stride * (4 * b + 3)] = cmulf(w, c[12 + b]);
        gw = cmulf(gw, w4);
    }
}

template<int DIR, bool HZ>
__device__ __forceinline__ void fft4096_ip(float2* s, int tid) {
    float2 c[16];
    const int rb = PHI(tid);
    {
#pragma unroll
        for (int m = 0; m < (HZ ? 8 : 16); m++) c[m] = s[rb + 272 * m];
        dft16ip<DIR, HZ>(c);
        float2 w1 = g_tw[tid];
        if (DIR < 0) w1.y = -w1.y;
        __syncthreads();
        store_tw(s, 17 * tid, 1, w1, c);
        __syncthreads();
    }
    {
#pragma unroll
        for (int m = 0; m < 16; m++) c[m] = s[rb + 272 * m];
        dft16ip<DIR, false>(c);
        float2 w1 = g_tw[tid & ~15];
        if (DIR < 0) w1.y = -w1.y;
        __syncthreads();
        store_tw(s, 17 * (tid & ~15) + (tid & 15), 17, w1, c);
        __syncthreads();
    }
    {
        // pass 2: each thread reads and writes the SAME address set -> no mid-pass sync
#pragma unroll
        for (int m = 0; m < 16; m++) c[m] = s[rb + 272 * m];
        dft16ip<DIR, false>(c);
#pragma unroll
        for (int slot = 0; slot < 16; slot++) {
            int m = 4 * (slot & 3) + (slot >> 2);
            s[rb + 272 * m] = c[slot];
        }
        __syncthreads();
    }
}

// ---------------- build kernel spectrum: interp + norm + rfft ----------------
__global__ void build_kf_kernel(const float* __restrict__ k0, const float* __restrict__ k1,
                                const float* __restrict__ k2, const float* __restrict__ k3,
                                const float* __restrict__ k4, const float* __restrict__ k5,
                                const float* __restrict__ k6) {
    extern __shared__ float2 smem[];
    float2* s = smem;
    __shared__ float red[8];
    int d = blockIdx.x;
    int tid = threadIdx.x;

    const float* segp[7] = {k0, k1, k2, k3, k4, k5, k6};

    float ss = 0.f;
    for (int t = tid; t < LSEQ; t += 256) {
        int seg, scale, off;
        if      (t < 64)   { seg = 0; scale = 1;  off = 0;    }
        else if (t < 128)  { seg = 1; scale = 1;  off = 64;   }
        else if (t < 256)  { seg = 2; scale = 2;  off = 128;  }
        else if (t < 512)  { seg = 3; scale = 4;  off = 256;  }
        else if (t < 1024) { seg = 4; scale = 8;  off = 512;  }
        else if (t < 2048) { seg = 5; scale = 16; off = 1024; }
        else               { seg = 6; scale = 32; off = 2048; }
        int j = t - off;
        float coord = ((float)j + 0.5f) / (float)scale - 0.5f;
        coord = fminf(fmaxf(coord, 0.f), 63.f);
        int lo = (int)coord;
        int hi = min(lo + 1, 63);
        float w = coord - (float)lo;
        const float* kp = segp[seg] + d * 64;
        float v = kp[lo] * (1.f - w) + kp[hi] * w;
        ((float*)s)[2 * PHI(t >> 1) + (t & 1)] = v;
        ss += v * v;
    }
    for (int o = 16; o > 0; o >>= 1) ss += __shfl_xor_sync(0xffffffffu, ss, o);
    if ((tid & 31) == 0) red[tid >> 5] = ss;
    __syncthreads();
    float tot = 0.f;
#pragma unroll
    for (int i = 0; i < 8; i++) tot += red[i];
    float sc = 1.0f / sqrtf(tot);

    for (int n = tid; n < NF / 2; n += 256) {
        float2 z = s[PHI(n)];
        s[PHI(n)] = make_float2(z.x * sc, z.y * sc);
    }
    __syncthreads();
    fft4096_ip<1, true>(s, tid);

    const float INV = 1.0f / 4096.0f;
    float2* Kf = g_Kf + (size_t)d * (MH + 1);
    for (int k = tid; k <= 2048; k += 256) {
        if (k == 0) {
            float2 Z0 = s[PHI(0)];
            Kf[0]  = make_float2((Z0.x + Z0.y) * INV, 0.f);
            Kf[MH] = make_float2((Z0.x - Z0.y) * INV, 0.f);
        } else if (k == 2048) {
            float2 Z = s[PHI(2048)];
            Kf[2048] = make_float2(Z.x * INV, -Z.y * INV);
        } else {
            float2 Za = s[PHI(k)], Zb = s[PHI(NF - k)];
            float2 E  = make_float2(0.5f * (Za.x + Zb.x), 0.5f * (Za.y - Zb.y));
            float2 Dm = make_float2(0.5f * (Za.x - Zb.x), 0.5f * (Za.y + Zb.y));
            float2 O  = make_float2(Dm.y, -Dm.x);
            float2 w  = g_tw2[k];
            float2 WO = cmulf(w, O);
            Kf[k]      = make_float2((E.x + WO.x) * INV, (E.y + WO.y) * INV);
            Kf[MH - k] = make_float2((E.x - WO.x) * INV, -(E.y - WO.y) * INV);
        }
    }
}

// ---------------- per-row conv ----------------
__global__ void __launch_bounds__(256, 4) conv_kernel(const float* __restrict__ u,
                                                      const float* __restrict__ Dv) {
    extern __shared__ float2 smem[];
    float2* s = smem;
    int row = blockIdx.x;            // b*DM + d
    int d = row & (DM - 1);
    int tid = threadIdx.x;
    const float2* u2 = (const float2*)(u + (size_t)row * LSEQ);

    for (int n = tid; n < 2048; n += 256) s[PHI(n)] = u2[n];
    __syncthreads();
    fft4096_ip<1, true>(s, tid);

    const float2* Kf = g_Kf + (size_t)d * (MH + 1);
    for (int k = tid; k <= 2048; k += 256) {
        if (k == 0) {
            float2 Z0 = s[PHI(0)];
            float X0 = Z0.x + Z0.y;
            float XM = Z0.x - Z0.y;
            float2 K0 = Kf[0], KM = Kf[MH];
            float2 Y0 = make_float2(X0 * K0.x, X0 * K0.y);
            float2 YM = make_float2(XM * KM.x, XM * KM.y);
            float2 Ep = make_float2(0.5f * (Y0.x + YM.x), 0.5f * (Y0.y - YM.y));
            float2 Op = make_float2(0.5f * (Y0.x - YM.x), 0.5f * (Y0.y + YM.y));
            s[PHI(0)] = make_float2(Ep.x - Op.y, Ep.y + Op.x);
        } else if (k == 2048) {
            float2 Z = s[PHI(2048)];
            float2 X = make_float2(Z.x, -Z.y);
            float2 Y = cmulf(X, Kf[2048]);
            s[PHI(2048)] = make_float2(Y.x, -Y.y);
        } else {
            float2 Za = s[PHI(k)], Zb = s[PHI(NF - k)];
            float2 E  = make_float2(0.5f * (Za.x + Zb.x), 0.5f * (Za.y - Zb.y));
            float2 Dm = make_float2(0.5f * (Za.x - Zb.x), 0.5f * (Za.y + Zb.y));
            float2 O  = make_float2(Dm.y, -Dm.x);
            float2 w  = g_tw2[k];
            float2 WO = cmulf(w, O);
            float2 Xa = make_float2(E.x + WO.x, E.y + WO.y);
            float2 Xb = make_float2(E.x - WO.x, -(E.y - WO.y));
            float2 Ya = cmulf(Xa, Kf[k]);
            float2 Yb = cmulf(Xb, Kf[MH - k]);
            float2 Ep = make_float2(0.5f * (Ya.x + Yb.x), 0.5f * (Ya.y - Yb.y));
            float2 Dp = make_float2(0.5f * (Ya.x - Yb.x), 0.5f * (Ya.y + Yb.y));
            float2 V  = make_float2(w.x, -w.y);
            float2 Op = cmulf(V, Dp);
            s[PHI(k)]      = make_float2(Ep.x - Op.y, Ep.y + Op.x);
            s[PHI(NF - k)] = make_float2(Ep.x + Op.y, Op.x - Ep.y);
        }
    }
    __syncthreads();
    fft4096_ip<-1, false>(s, tid);

    float Dd = Dv[d];
    __half2* gout = (__half2*)(g_gh + (size_t)row * LSEQ);
#pragma unroll 1
    for (int n = tid; n < 2048; n += 256) {
        float2 z = s[PHI(n)];
        float2 uu = u2[n];
        float x0 = z.x + uu.x * Dd;
        float x1 = z.y + uu.y * Dd;
        float g0 = 0.5f * x0 * (1.f + erff(x0 * 0.70710678118654752f));
        float g1 = 0.5f * x1 * (1.f + erff(x1 * 0.70710678118654752f));
        gout[n] = __floats2half2_rn(g0, g1);
    }
}

// ---------------- fp16 tensor-core GEMM: out[b,v,l] = sum_u W[v,u] g[b,u,l] + bias[v] ----
// m16n8k16; BM=128 x BN=128 x BK=64, 256 threads, 3-stage cp.async, 2 CTAs/SM.
// B fragments for ALL four k16-steps batch-prefetched (MLP=8 on ldsm).
#define BM 128
#define BN 128
#define BK 64
#define SAH 72    // A row stride (halves): [v][kk]
#define SBH 136   // B row stride (halves): [kk][l]
#define A_SZH (BM * SAH)             // 9216 halves
#define B_SZH (BK * SBH)             // 8704 halves
#define STG_H (A_SZH + B_SZH)        // 17920 halves = 35840 B
#define NSTG 3
#define SMEM_GEMM (NSTG * STG_H * 2) // 107520 B
#define NIT (DM / BK)                // 16

__device__ __forceinline__ void cpa16(void* s, const void* g) {
    unsigned sa = (unsigned)__cvta_generic_to_shared(s);
    asm volatile("cp.async.cg.shared.global [%0], [%1], 16;\n" :: "r"(sa), "l"(g));
}
__device__ __forceinline__ void ldsm4(unsigned& r0, unsigned& r1, unsigned& r2, unsigned& r3,
                                      const void* p) {
    unsigned a = (unsigned)__cvta_generic_to_shared(p);
    asm volatile("ldmatrix.sync.aligned.m8n8.x4.shared.b16 {%0,%1,%2,%3}, [%4];\n"
                 : "=r"(r0), "=r"(r1), "=r"(r2), "=r"(r3) : "r"(a));
}
__device__ __forceinline__ void ldsm4t(unsigned& r0, unsigned& r1, unsigned& r2, unsigned& r3,
                                       const void* p) {
    unsigned a = (unsigned)__cvta_generic_to_shared(p);
    asm volatile("ldmatrix.sync.aligned.m8n8.x4.trans.shared.b16 {%0,%1,%2,%3}, [%4];\n"
                 : "=r"(r0), "=r"(r1), "=r"(r2), "=r"(r3) : "r"(a));
}

__global__ void __launch_bounds__(256, 2) gemm_kernel(const float* __restrict__ bias,
                                                      float* __restrict__ out) {
    extern __shared__ __half hsm[];

    int b  = blockIdx.z;
    int v0 = blockIdx.y * BM;
    int l0 = blockIdx.x * BN;
    int tid = threadIdx.x;
    int wid = tid >> 5, lane = tid & 31;
    int wm = wid >> 2, wn = wid & 3;         // 2x4 warp grid; warp tile 64(v) x 32(l)
    int grp = lane >> 2, qid = lane & 3;

    const __half* gbase = g_gh + (size_t)b * DM * LSEQ;

    float acc[4][4][4];
#pragma unroll
    for (int i = 0; i < 4; i++)
#pragma unroll
        for (int j = 0; j < 4; j++)
#pragma unroll
            for (int r = 0; r < 4; r++) acc[i][j][r] = 0.f;

    auto stage_load = [&](int st, int u0) {
        __half* As = hsm + st * STG_H;
        __half* Bs = As + A_SZH;
#pragma unroll
        for (int rep = 0; rep < 4; rep++) {          // A: 128 rows x 64 halves (8 x 16B/row)
            int idx = rep * 256 + tid;
            int r = idx >> 3, c = idx & 7;
            cpa16(As + r * SAH + c * 8, g_Wh + (size_t)(v0 + r) * DM + u0 + c * 8);
        }
#pragma unroll
        for (int rep = 0; rep < 4; rep++) {          // B: 64 rows x 128 halves (16 x 16B/row)
            int idx = rep * 256 + tid;
            int r = idx >> 4, c = idx & 15;
            cpa16(Bs + r * SBH + c * 8, gbase + (size_t)(u0 + r) * LSEQ + l0 + c * 8);
        }
        asm volatile("cp.async.commit_group;\n");
    };

    // prologue: fill 2 of 3 stages
    stage_load(0, 0);
    stage_load(1, BK);

    for (int it = 0; it < NIT; it++) {
        if (it < NIT - 1) {
            asm volatile("cp.async.wait_group 1;\n");   // stage(it) ready
        } else {
            asm volatile("cp.async.wait_group 0;\n");
        }
        __syncthreads();                                // all warps done with stage (it+2)%3
        if (it + 2 < NIT) stage_load((it + 2) % 3, (it + 2) * BK);

        const __half* A   = hsm + (it % 3) * STG_H;
        const __half* Bsm = A + A_SZH;

        // batch-prefetch B fragments for ALL four k16-steps (8 back-to-back ldsm)
        unsigned bf[4][4][2];                           // [ks][nt][2]
#pragma unroll
        for (int ks = 0; ks < 4; ks++) {
            int kk = ks * 16;
            int mrow = kk + (lane & 7) + ((lane & 8) ? 8 : 0);
#pragma unroll
            for (int p = 0; p < 2; p++) {
                int mcol = wn * 32 + p * 16 + ((lane & 16) ? 8 : 0);
                unsigned r0, r1, r2, r3;
                ldsm4t(r0, r1, r2, r3, Bsm + mrow * SBH + mcol);
                bf[ks][p * 2 + 0][0] = r0; bf[ks][p * 2 + 0][1] = r1;
                bf[ks][p * 2 + 1][0] = r2; bf[ks][p * 2 + 1][1] = r3;
            }
        }
#pragma unroll
        for (int ks = 0; ks < 4; ks++) {                // four k16 steps per BK=64
            int kk = ks * 16;
#pragma unroll
            for (int mt = 0; mt < 4; mt++) {
                int rowa = wm * 64 + mt * 16 + (lane & 15);
                int cola = kk + ((lane & 16) ? 8 : 0);
                unsigned a0, a1, a2, a3;
                ldsm4(a0, a1, a2, a3, A + rowa * SAH + cola);
#pragma unroll
                for (int nt = 0; nt < 4; nt++) {
                    asm volatile(
                        "mma.sync.aligned.m16n8k16.row.col.f32.f16.f16.f32 "
                        "{%0,%1,%2,%3}, {%4,%5,%6,%7}, {%8,%9}, {%0,%1,%2,%3};\n"
                        : "+f"(acc[mt][nt][0]), "+f"(acc[mt][nt][1]),
                          "+f"(acc[mt][nt][2]), "+f"(acc[mt][nt][3])
                        : "r"(a0), "r"(a1), "r"(a2), "r"(a3),
                          "r"(bf[ks][nt][0]), "r"(bf[ks][nt][1]));
                }
            }
        }
    }
#pragma unroll
    for (int mt = 0; mt < 4; mt++) {
        int v = v0 + wm * 64 + mt * 16 + grp;
        float bi0 = bias[v], bi1 = bias[v + 8];
#pragma unroll
        for (int nt = 0; nt < 4; nt++) {
            int l = l0 + wn * 32 + nt * 8 + qid * 2;
            float2* o0 = (float2*)(out + ((size_t)b * DM + v) * LSEQ + l);
            float2* o1 = (float2*)(out + ((size_t)b * DM + v + 8) * LSEQ + l);
            *o0 = make_float2(acc[mt][nt][0] + bi0, acc[mt][nt][1] + bi0);
            *o1 = make_float2(acc[mt][nt][2] + bi1, acc[mt][nt][3] + bi1);
        }
    }
}

// ---------------- launch ----------------
extern "C" void kernel_launch(void* const* d_in, const int* in_sizes, int n_in,
                              void* d_out, int out_size) {
    const float* u  = (const float*)d_in[0];
    const float* k0 = (const float*)d_in[1];
    const float* k1 = (const float*)d_in[2];
    const float* k2 = (const float*)d_in[3];
    const float* k3 = (const float*)d_in[4];
    const float* k4 = (const float*)d_in[5];
    const float* k5 = (const float*)d_in[6];
    const float* k6 = (const float*)d_in[7];
    const float* Dv = (const float*)d_in[8];
    const float* W  = (const float*)d_in[9];
    const float* bi = (const float*)d_in[10];
    float* out = (float*)d_out;

    const int smem_fft = SBUF * (int)sizeof(float2);                 // 34816 B
    cudaFuncSetAttribute(conv_kernel, cudaFuncAttributeMaxDynamicSharedMemorySize, smem_fft);
    cudaFuncSetAttribute(build_kf_kernel, cudaFuncAttributeMaxDynamicSharedMemorySize, smem_fft);
    cudaFuncSetAttribute(gemm_kernel, cudaFuncAttributeMaxDynamicSharedMemorySize, SMEM_GEMM);

    init_all_kernel<<<DM * DM / 256, 256>>>(W);
    build_kf_kernel<<<DM, 256, smem_fft>>>(k0, k1, k2, k3, k4, k5, k6);
    conv_kernel<<<BB * DM, 256, smem_fft>>>(u, Dv);
    dim3 gg(LSEQ / BN, DM / BM, BB);
    gemm_kernel<<<gg, 256, SMEM_GEMM>>>(bi, out);
}

// round 15
// speedup vs baseline: 1.0364x; 1.0027x over previous
#include <cuda_runtime.h>
#include <cuda_fp16.h>
#include <cstdint>
#include <math.h>

#define LSEQ 4096
#define DM   1024
#define BB   8
#define NF   4096          // complex FFT size (real FFT of 8192 via packing)
#define MH   4096          // half of 8192
#define SBUF 4352          // padded in-place buffer: 17 * 256 float2

// padded index map (avoids 128B-stride bank conflicts)
#define PHI(i) ((((i) >> 4) * 17) + ((i) & 15))

// ---------------- device scratch (no allocations allowed) ----------------
__device__ float2  g_Kf[DM * (MH + 1)];                 // kernel spectra (pre-scaled by 1/4096)
__device__ __half  g_gh[(size_t)BB * DM * LSEQ];        // gelu output as fp16
__device__ __half  g_Wh[DM * DM];                       // W as fp16
__device__ float2  g_tw[NF / 2];                        // e^{-2pi i j/4096}
__device__ float2  g_tw2[MH / 2 + 1];                   // e^{-2pi i k/8192}

__device__ __forceinline__ float2 cmulf(float2 a, float2 b) {
    return make_float2(a.x * b.x - a.y * b.y, a.x * b.y + a.y * b.x);
}

// ---------------- fused init: twiddle tables + W->fp16 ----------------
__global__ void init_all_kernel(const float* __restrict__ W) {
    int i = blockIdx.x * blockDim.x + threadIdx.x;
    if (i < NF / 2) {
        float a = (float)i / (float)(NF / 2);
        g_tw[i] = make_float2(cospif(a), -sinpif(a));
    }
    if (i <= MH / 2) {
        float a = (float)i / (float)MH;
        g_tw2[i] = make_float2(cospif(a), -sinpif(a));
    }
    if (i < DM * DM) g_Wh[i] = __float2half(W[i]);
}

// ---------------- in-place 16-point DFT (two radix-4 stages) ----------------
template<int DIR, bool HZ>
__device__ __forceinline__ void dft16ip(float2* c) {
    const float d  = (float)DIR;
    const float C1 = 0.92387953251128674f;
    const float Sn = 0.38268343236508978f;
    const float HF = 0.70710678118654752f;
#pragma unroll
    for (int r1 = 0; r1 < 4; r1++) {
        float2 a = c[r1], b = c[r1 + 4];
        if (HZ) {
            c[r1]      = make_float2(a.x + b.x, a.y + b.y);
            c[r1 + 4]  = make_float2(a.x + d * b.y, a.y - d * b.x);
            c[r1 + 8]  = make_float2(a.x - b.x, a.y - b.y);
            c[r1 + 12] = make_float2(a.x - d * b.y, a.y + d * b.x);
        } else {
            float2 e = c[r1 + 8], f = c[r1 + 12];
            float2 t0 = make_float2(a.x + e.x, a.y + e.y);
            float2 t1 = make_float2(a.x - e.x, a.y - e.y);
            float2 t2 = make_float2(b.x + f.x, b.y + f.y);
            float2 t3 = make_float2(b.x - f.x, b.y - f.y);
            c[r1]      = make_float2(t0.x + t2.x, t0.y + t2.y);
            c[r1 + 8]  = make_float2(t0.x - t2.x, t0.y - t2.y);
            c[r1 + 4]  = make_float2(t1.x + d * t3.y, t1.y - d * t3.x);
            c[r1 + 12] = make_float2(t1.x - d * t3.y, t1.y + d * t3.x);
        }
    }
    const float2 e1 = make_float2(C1,  -d * Sn);
    const float2 e2 = make_float2(HF,  -d * HF);
    const float2 e3 = make_float2(Sn,  -d * C1);
    const float2 e6 = make_float2(-HF, -d * HF);
    const float2 e9 = make_float2(-C1,  d * Sn);
    c[5]  = cmulf(c[5],  e1);
    c[9]  = cmulf(c[9],  e2);
    c[13] = cmulf(c[13], e3);
    c[6]  = cmulf(c[6],  e2);
    c[10] = make_float2(d * c[10].y, -d * c[10].x);
    c[14] = cmulf(c[14], e6);
    c[7]  = cmulf(c[7],  e3);
    c[11] = cmulf(c[11], e6);
    c[15] = cmulf(c[15], e9);
#pragma unroll
    for (int m2 = 0; m2 < 4; m2++) {
        float2 u0 = c[4 * m2], u1 = c[4 * m2 + 1], u2 = c[4 * m2 + 2], u3 = c[4 * m2 + 3];
        float2 t0 = make_float2(u0.x + u2.x, u0.y + u2.y);
        float2 t1 = make_float2(u0.x - u2.x, u0.y - u2.y);
        float2 t2 = make_float2(u1.x + u3.x, u1.y + u3.y);
        float2 t3 = make_float2(u1.x - u3.x, u1.y - u3.y);
        c[4 * m2]     = make_float2(t0.x + t2.x, t0.y + t2.y);
        c[4 * m2 + 2] = make_float2(t0.x - t2.x, t0.y - t2.y);
        c[4 * m2 + 1] = make_float2(t1.x + d * t3.y, t1.y - d * t3.x);
        c[4 * m2 + 3] = make_float2(t1.x - d * t3.y, t1.y + d * t3.x);
    }
}

__device__ __forceinline__ void store_tw(float2* s, int wbase, int stride,
                                         float2 w1, const float2* c) {
    float2 w2 = cmulf(w1, w1);
    float2 w4 = cmulf(w2, w2);
    float2 gw = make_float2(1.f, 0.f);
#pragma unroll
    for (int b = 0; b < 4; b++) {
        float2 w = gw;
        s[wbase + stride * (4 * b + 0)] = cmulf(w, c[b]);
        w = cmulf(w, w1);
        s[wbase + stride * (4 * b + 1)] = cmulf(w, c[4 + b]);
        w = cmulf(w, w1);
        s[wbase + stride * (4 * b + 2)] = cmulf(w, c[8 + b]);
        w = cmulf(w, w1);
        s[wbase + stride * (4 * b + 3)] = cmulf(w, c[12 + b]);
        gw = cmulf(gw, w4);
    }
}

template<int DIR, bool HZ>
__device__ __forceinline__ void fft4096_ip(float2* s, int tid) {
    float2 c[16];
    const int rb = PHI(tid);
    {
#pragma unroll
        for (int m = 0; m < (HZ ? 8 : 16); m++) c[m] = s[rb + 272 * m];
        dft16ip<DIR, HZ>(c);
        float2 w1 = g_tw[tid];
        if (DIR < 0) w1.y = -w1.y;
        __syncthreads();
        store_tw(s, 17 * tid, 1, w1, c);
        __syncthreads();
    }
    {
#pragma unroll
        for (int m = 0; m < 16; m++) c[m] = s[rb + 272 * m];
        dft16ip<DIR, false>(c);
        float2 w1 = g_tw[tid & ~15];
        if (DIR < 0) w1.y = -w1.y;
        __syncthreads();
        store_tw(s, 17 * (tid & ~15) + (tid & 15), 17, w1, c);
        __syncthreads();
    }
    {
        // pass 2: each thread reads and writes the SAME address set -> no mid-pass sync
#pragma unroll
        for (int m = 0; m < 16; m++) c[m] = s[rb + 272 * m];
        dft16ip<DIR, false>(c);
#pragma unroll
        for (int slot = 0; slot < 16; slot++) {
            int m = 4 * (slot & 3) + (slot >> 2);
            s[rb + 272 * m] = c[slot];
        }
        __syncthreads();
    }
}

// ---------------- build kernel spectrum: interp + norm + rfft ----------------
__global__ void build_kf_kernel(const float* __restrict__ k0, const float* __restrict__ k1,
                                const float* __restrict__ k2, const float* __restrict__ k3,
                                const float* __restrict__ k4, const float* __restrict__ k5,
                                const float* __restrict__ k6) {
    extern __shared__ float2 smem[];
    float2* s = smem;
    __shared__ float red[8];
    int d = blockIdx.x;
    int tid = threadIdx.x;

    const float* segp[7] = {k0, k1, k2, k3, k4, k5, k6};

    float ss = 0.f;
    for (int t = tid; t < LSEQ; t += 256) {
        int seg, scale, off;
        if      (t < 64)   { seg = 0; scale = 1;  off = 0;    }
        else if (t < 128)  { seg = 1; scale = 1;  off = 64;   }
        else if (t < 256)  { seg = 2; scale = 2;  off = 128;  }
        else if (t < 512)  { seg = 3; scale = 4;  off = 256;  }
        else if (t < 1024) { seg = 4; scale = 8;  off = 512;  }
        else if (t < 2048) { seg = 5; scale = 16; off = 1024; }
        else               { seg = 6; scale = 32; off = 2048; }
        int j = t - off;
        float coord = ((float)j + 0.5f) / (float)scale - 0.5f;
        coord = fminf(fmaxf(coord, 0.f), 63.f);
        int lo = (int)coord;
        int hi = min(lo + 1, 63);
        float w = coord - (float)lo;
        const float* kp = segp[seg] + d * 64;
        float v = kp[lo] * (1.f - w) + kp[hi] * w;
        ((float*)s)[2 * PHI(t >> 1) + (t & 1)] = v;
        ss += v * v;
    }
    for (int o = 16; o > 0; o >>= 1) ss += __shfl_xor_sync(0xffffffffu, ss, o);
    if ((tid & 31) == 0) red[tid >> 5] = ss;
    __syncthreads();
    float tot = 0.f;
#pragma unroll
    for (int i = 0; i < 8; i++) tot += red[i];
    float sc = 1.0f / sqrtf(tot);

    for (int n = tid; n < NF / 2; n += 256) {
        float2 z = s[PHI(n)];
        s[PHI(n)] = make_float2(z.x * sc, z.y * sc);
    }
    __syncthreads();
    fft4096_ip<1, true>(s, tid);

    const float INV = 1.0f / 4096.0f;
    float2* Kf = g_Kf + (size_t)d * (MH + 1);
    for (int k = tid; k <= 2048; k += 256) {
        if (k == 0) {
            float2 Z0 = s[PHI(0)];
            Kf[0]  = make_float2((Z0.x + Z0.y) * INV, 0.f);
            Kf[MH] = make_float2((Z0.x - Z0.y) * INV, 0.f);
        } else if (k == 2048) {
            float2 Z = s[PHI(2048)];
            Kf[2048] = make_float2(Z.x * INV, -Z.y * INV);
        } else {
            float2 Za = s[PHI(k)], Zb = s[PHI(NF - k)];
            float2 E  = make_float2(0.5f * (Za.x + Zb.x), 0.5f * (Za.y - Zb.y));
            float2 Dm = make_float2(0.5f * (Za.x - Zb.x), 0.5f * (Za.y + Zb.y));
            float2 O  = make_float2(Dm.y, -Dm.x);
            float2 w  = g_tw2[k];
            float2 WO = cmulf(w, O);
            Kf[k]      = make_float2((E.x + WO.x) * INV, (E.y + WO.y) * INV);
            Kf[MH - k] = make_float2((E.x - WO.x) * INV, -(E.y - WO.y) * INV);
        }
    }
}

// ---------------- per-row conv ----------------
__global__ void __launch_bounds__(256, 4) conv_kernel(const float* __restrict__ u,
                                                      const float* __restrict__ Dv) {
    extern __shared__ float2 smem[];
    float2* s = smem;
    int row = blockIdx.x;            // b*DM + d
    int d = row & (DM - 1);
    int tid = threadIdx.x;
    const float2* u2 = (const float2*)(u + (size_t)row * LSEQ);

    for (int n = tid; n < 2048; n += 256) s[PHI(n)] = u2[n];
    __syncthreads();
    fft4096_ip<1, true>(s, tid);

    const float2* Kf = g_Kf + (size_t)d * (MH + 1);
    for (int k = tid; k <= 2048; k += 256) {
        if (k == 0) {
            float2 Z0 = s[PHI(0)];
            float X0 = Z0.x + Z0.y;
            float XM = Z0.x - Z0.y;
            float2 K0 = Kf[0], KM = Kf[MH];
            float2 Y0 = make_float2(X0 * K0.x, X0 * K0.y);
            float2 YM = make_float2(XM * KM.x, XM * KM.y);
            float2 Ep = make_float2(0.5f * (Y0.x + YM.x), 0.5f * (Y0.y - YM.y));
            float2 Op = make_float2(0.5f * (Y0.x - YM.x), 0.5f * (Y0.y + YM.y));
            s[PHI(0)] = make_float2(Ep.x - Op.y, Ep.y + Op.x);
        } else if (k == 2048) {
            float2 Z = s[PHI(2048)];
            float2 X = make_float2(Z.x, -Z.y);
            float2 Y = cmulf(X, Kf[2048]);
            s[PHI(2048)] = make_float2(Y.x, -Y.y);
        } else {
            float2 Za = s[PHI(k)], Zb = s[PHI(NF - k)];
            float2 E  = make_float2(0.5f * (Za.x + Zb.x), 0.5f * (Za.y - Zb.y));
            float2 Dm = make_float2(0.5f * (Za.x - Zb.x), 0.5f * (Za.y + Zb.y));
            float2 O  = make_float2(Dm.y, -Dm.x);
            float2 w  = g_tw2[k];
            float2 WO = cmulf(w, O);
            float2 Xa = make_float2(E.x + WO.x, E.y + WO.y);
            float2 Xb = make_float2(E.x - WO.x, -(E.y - WO.y));
            float2 Ya = cmulf(Xa, Kf[k]);
            float2 Yb = cmulf(Xb, Kf[MH - k]);
            float2 Ep = make_float2(0.5f * (Ya.x + Yb.x), 0.5f * (Ya.y - Yb.y));
            float2 Dp = make_float2(0.5f * (Ya.x - Yb.x), 0.5f * (Ya.y + Yb.y));
            float2 V  = make_float2(w.x, -w.y);
            float2 Op = cmulf(V, Dp);
            s[PHI(k)]      = make_float2(Ep.x - Op.y, Ep.y + Op.x);
            s[PHI(NF - k)] = make_float2(Ep.x + Op.y, Op.x - Ep.y);
        }
    }
    __syncthreads();
    fft4096_ip<-1, false>(s, tid);

    float Dd = Dv[d];
    __half2* gout = (__half2*)(g_gh + (size_t)row * LSEQ);
#pragma unroll 1
    for (int n = tid; n < 2048; n += 256) {
        float2 z = s[PHI(n)];
        float2 uu = u2[n];
        float x0 = z.x + uu.x * Dd;
        float x1 = z.y + uu.y * Dd;
        float g0 = 0.5f * x0 * (1.f + erff(x0 * 0.70710678118654752f));
        float g1 = 0.5f * x1 * (1.f + erff(x1 * 0.70710678118654752f));
        gout[n] = __floats2half2_rn(g0, g1);
    }
}

// ---------------- fp16 tensor-core GEMM: out[b,v,l] = sum_u W[v,u] g[b,u,l] + bias[v] ----
// m16n8k16; BM=128 x BN=128 x BK=64, 256 threads, 3-stage cp.async, 2 CTAs/SM.
// B fragments for ALL four k16-steps batch-prefetched (MLP=8 on ldsm).
#define BM 128
#define BN 128
#define BK 64
#define SAH 72    // A row stride (halves): [v][kk]
#define SBH 136   // B row stride (halves): [kk][l]
#define A_SZH (BM * SAH)             // 9216 halves
#define B_SZH (BK * SBH)             // 8704 halves
#define STG_H (A_SZH + B_SZH)        // 17920 halves = 35840 B
#define NSTG 3
#define SMEM_GEMM (NSTG * STG_H * 2) // 107520 B
#define NIT (DM / BK)                // 16

__device__ __forceinline__ void cpa16(void* s, const void* g) {
    unsigned sa = (unsigned)__cvta_generic_to_shared(s);
    asm volatile("cp.async.cg.shared.global [%0], [%1], 16;\n" :: "r"(sa), "l"(g));
}
__device__ __forceinline__ void ldsm4(unsigned& r0, unsigned& r1, unsigned& r2, unsigned& r3,
                                      const void* p) {
    unsigned a = (unsigned)__cvta_generic_to_shared(p);
    asm volatile("ldmatrix.sync.aligned.m8n8.x4.shared.b16 {%0,%1,%2,%3}, [%4];\n"
                 : "=r"(r0), "=r"(r1), "=r"(r2), "=r"(r3) : "r"(a));
}
__device__ __forceinline__ void ldsm4t(unsigned& r0, unsigned& r1, unsigned& r2, unsigned& r3,
                                       const void* p) {
    unsigned a = (unsigned)__cvta_generic_to_shared(p);
    asm volatile("ldmatrix.sync.aligned.m8n8.x4.trans.shared.b16 {%0,%1,%2,%3}, [%4];\n"
                 : "=r"(r0), "=r"(r1), "=r"(r2), "=r"(r3) : "r"(a));
}

__global__ void __launch_bounds__(256, 2) gemm_kernel(const float* __restrict__ bias,
                                                      float* __restrict__ out) {
    extern __shared__ __half hsm[];

    int b  = blockIdx.z;
    int v0 = blockIdx.y * BM;
    int l0 = blockIdx.x * BN;
    int tid = threadIdx.x;
    int wid = tid >> 5, lane = tid & 31;
    int wm = wid >> 2, wn = wid & 3;         // 2x4 warp grid; warp tile 64(v) x 32(l)
    int grp = lane >> 2, qid = lane & 3;

    const __half* gbase = g_gh + (size_t)b * DM * LSEQ;

    float acc[4][4][4];
#pragma unroll
    for (int i = 0; i < 4; i++)
#pragma unroll
        for (int j = 0; j < 4; j++)
#pragma unroll
            for (int r = 0; r < 4; r++) acc[i][j][r] = 0.f;

    auto stage_load = [&](int st, int u0) {
        __half* As = hsm + st * STG_H;
        __half* Bs = As + A_SZH;
#pragma unroll
        for (int rep = 0; rep < 4; rep++) {          // A: 128 rows x 64 halves (8 x 16B/row)
            int idx = rep * 256 + tid;
            int r = idx >> 3, c = idx & 7;
            cpa16(As + r * SAH + c * 8, g_Wh + (size_t)(v0 + r) * DM + u0 + c * 8);
        }
#pragma unroll
        for (int rep = 0; rep < 4; rep++) {          // B: 64 rows x 128 halves (16 x 16B/row)
            int idx = rep * 256 + tid;
            int r = idx >> 4, c = idx & 15;
            cpa16(Bs + r * SBH + c * 8, gbase + (size_t)(u0 + r) * LSEQ + l0 + c * 8);
        }
        asm volatile("cp.async.commit_group;\n");
    };

    // prologue: fill 2 of 3 stages
    stage_load(0, 0);
    stage_load(1, BK);

    for (int it = 0; it < NIT; it++) {
        if (it < NIT - 1) {
            asm volatile("cp.async.wait_group 1;\n");   // stage(it) ready
        } else {
            asm volatile("cp.async.wait_group 0;\n");
        }
        __syncthreads();                                // all warps done with stage (it+2)%3
        if (it + 2 < NIT) stage_load((it + 2) % 3, (it + 2) * BK);

        const __half* A   = hsm + (it % 3) * STG_H;
        const __half* Bsm = A + A_SZH;

        // batch-prefetch B fragments for ALL four k16-steps (8 back-to-back ldsm)
        unsigned bf[4][4][2];                           // [ks][nt][2]
#pragma unroll
        for (int ks = 0; ks < 4; ks++) {
            int kk = ks * 16;
            int mrow = kk + (lane & 7) + ((lane & 8) ? 8 : 0);
#pragma unroll
            for (int p = 0; p < 2; p++) {
                int mcol = wn * 32 + p * 16 + ((lane & 16) ? 8 : 0);
                unsigned r0, r1, r2, r3;
                ldsm4t(r0, r1, r2, r3, Bsm + mrow * SBH + mcol);
                bf[ks][p * 2 + 0][0] = r0; bf[ks][p * 2 + 0][1] = r1;
                bf[ks][p * 2 + 1][0] = r2; bf[ks][p * 2 + 1][1] = r3;
            }
        }
#pragma unroll
        for (int ks = 0; ks < 4; ks++) {                // four k16 steps per BK=64
            int kk = ks * 16;
#pragma unroll
            for (int mt = 0; mt < 4; mt++) {
                int rowa = wm * 64 + mt * 16 + (lane & 15);
                int cola = kk + ((lane & 16) ? 8 : 0);
                unsigned a0, a1, a2, a3;
                ldsm4(a0, a1, a2, a3, A + rowa * SAH + cola);
#pragma unroll
                for (int nt = 0; nt < 4; nt++) {
                    asm volatile(
                        "mma.sync.aligned.m16n8k16.row.col.f32.f16.f16.f32 "
                        "{%0,%1,%2,%3}, {%4,%5,%6,%7}, {%8,%9}, {%0,%1,%2,%3};\n"
                        : "+f"(acc[mt][nt][0]), "+f"(acc[mt][nt][1]),
                          "+f"(acc[mt][nt][2]), "+f"(acc[mt][nt][3])
                        : "r"(a0), "r"(a1), "r"(a2), "r"(a3),
                          "r"(bf[ks][nt][0]), "r"(bf[ks][nt][1]));
                }
            }
        }
    }
#pragma unroll
    for (int mt = 0; mt < 4; mt++) {
        int v = v0 + wm * 64 + mt * 16 + grp;
        float bi0 = bias[v], bi1 = bias[v + 8];
#pragma unroll
        for (int nt = 0; nt < 4; nt++) {
            int l = l0 + wn * 32 + nt * 8 + qid * 2;
            float2* o0 = (float2*)(out + ((size_t)b * DM + v) * LSEQ + l);
            float2* o1 = (float2*)(out + ((size_t)b * DM + v + 8) * LSEQ + l);
            *o0 = make_float2(acc[mt][nt][0] + bi0, acc[mt][nt][1] + bi0);
            *o1 = make_float2(acc[mt][nt][2] + bi1, acc[mt][nt][3] + bi1);
        }
    }
}

// ---------------- launch ----------------
extern "C" void kernel_launch(void* const* d_in, const int* in_sizes, int n_in,
                              void* d_out, int out_size) {
    const float* u  = (const float*)d_in[0];
    const float* k0 = (const float*)d_in[1];
    const float* k1 = (const float*)d_in[2];
    const float* k2 = (const float*)d_in[3];
    const float* k3 = (const float*)d_in[4];
    const float* k4 = (const float*)d_in[5];
    const float* k5 = (const float*)d_in[6];
    const float* k6 = (const float*)d_in[7];
    const float* Dv = (const float*)d_in[8];
    const float* W  = (const float*)d_in[9];
    const float* bi = (const float*)d_in[10];
    float* out = (float*)d_out;

    const int smem_fft = SBUF * (int)sizeof(float2);                 // 34816 B
    cudaFuncSetAttribute(conv_kernel, cudaFuncAttributeMaxDynamicSharedMemorySize, smem_fft);
    cudaFuncSetAttribute(build_kf_kernel, cudaFuncAttributeMaxDynamicSharedMemorySize, smem_fft);
    cudaFuncSetAttribute(gemm_kernel, cudaFuncAttributeMaxDynamicSharedMemorySize, SMEM_GEMM);

    init_all_kernel<<<DM * DM / 256, 256>>>(W);
    build_kf_kernel<<<DM, 256, smem_fft>>>(k0, k1, k2, k3, k4, k5, k6);
    conv_kernel<<<BB * DM, 256, smem_fft>>>(u, Dv);
    dim3 gg(LSEQ / BN, DM / BM, BB);
    gemm_kernel<<<gg, 256, SMEM_GEMM>>>(bi, out);
}